// round 15
// baseline (speedup 1.0000x reference)
#include <cuda_runtime.h>
#include <cuda_fp16.h>
#include <cstdint>

#define DM 2048   // d_model
#define BATCH 2048
#define NT 64     // num transforms
#define RK 32     // rank

// ---------------------------------------------------------------------------
// Static device scratch (no allocation allowed). Single fp16 operand copies.
// ---------------------------------------------------------------------------
__device__ __half g_x16[BATCH * DM];    // x          [b][d]
__device__ __half g_v16[DM * DM];       // V_flat     [k][d]
__device__ __half g_w16[DM * DM];       // Wt = U^T   [d][k]
__device__ __half g_gv16[BATCH * DM];   // gated Vx   [b][k]
__device__ float g_vpart[1024];         // per-block sum-of-squares partials (V)
__device__ float g_upart[1024];         // per-block partials (U): [n*16 + dblk]
__device__ float g_gpart8[8 * BATCH * NT];  // gate split-K partials (4 MB)

// ---------------------------------------------------------------------------
// PTX helpers (portable sm_80 subset; ptxas here targets plain sm_103)
// ---------------------------------------------------------------------------
__device__ __forceinline__ uint32_t smem_u32(const void* p) {
    return (uint32_t)__cvta_generic_to_shared(p);
}
__device__ __forceinline__ void cp16(uint32_t dst, const void* src) {
    asm volatile("cp.async.cg.shared.global [%0], [%1], 16;\n" :: "r"(dst), "l"(src));
}
__device__ __forceinline__ void cp_commit() {
    asm volatile("cp.async.commit_group;\n" ::: "memory");
}
template<int N>
__device__ __forceinline__ void cp_wait() {
    asm volatile("cp.async.wait_group %0;\n" :: "n"(N) : "memory");
}
__device__ __forceinline__ void ldsm4(uint32_t* r, uint32_t addr) {
    asm volatile("ldmatrix.sync.aligned.m8n8.x4.shared.b16 {%0,%1,%2,%3}, [%4];"
                 : "=r"(r[0]), "=r"(r[1]), "=r"(r[2]), "=r"(r[3]) : "r"(addr));
}
__device__ __forceinline__ void mma_f16(float* d, const uint32_t* a, const uint32_t* b) {
    asm volatile(
        "mma.sync.aligned.m16n8k16.row.col.f32.f16.f16.f32 "
        "{%0,%1,%2,%3}, {%4,%5,%6,%7}, {%8,%9}, {%0,%1,%2,%3};"
        : "+f"(d[0]), "+f"(d[1]), "+f"(d[2]), "+f"(d[3])
        : "r"(a[0]), "r"(a[1]), "r"(a[2]), "r"(a[3]), "r"(b[0]), "r"(b[1]));
}
__device__ __forceinline__ uint32_t h2u(__half2 h) { return *(uint32_t*)&h; }

// ---------------------------------------------------------------------------
// Launch 1 (merged): gate-from-fp32 [0,128) + x convert [128,1152)
//                    + V convert/norms [1152,2176).
// __launch_bounds__(256, 3): cap regs (~85) so the 2048 memory-bound convert
// blocks get 3 CTAs/SM. The 128 gate-MMA blocks spill slightly; they are not
// the makespan.
// ---------------------------------------------------------------------------
__global__ __launch_bounds__(256, 3) void gate_prep(
    const float* __restrict__ x, const float* __restrict__ enc,
    const float4* __restrict__ xv, const float4* __restrict__ v)
{
    __shared__ __align__(1024) char sm[12288];   // A 8K | E 4K (single stage)
    __shared__ float red[256];

    const int bid = blockIdx.x;
    const int tid = threadIdx.x;

    if (bid >= 1152) {                      // ---- V + norm partials ----
        int vb = bid - 1152;                // 0..1023
        float4 w[4];
        #pragma unroll
        for (int j = 0; j < 4; j++) w[j] = v[vb * 1024 + j * 256 + tid];
        float s = 0.0f;
        #pragma unroll
        for (int j = 0; j < 4; j++) {
            int i = vb * 1024 + j * 256 + tid;
            __half2 a = __floats2half2_rn(w[j].x, w[j].y);
            __half2 b = __floats2half2_rn(w[j].z, w[j].w);
            ((uint2*)g_v16)[i] = make_uint2(h2u(a), h2u(b));
            s += w[j].x*w[j].x + w[j].y*w[j].y + w[j].z*w[j].z + w[j].w*w[j].w;
        }
        red[tid] = s;
        __syncthreads();
        for (int off = 128; off > 0; off >>= 1) {
            if (tid < off) red[tid] += red[tid + off];
            __syncthreads();
        }
        if (tid == 0) g_vpart[vb] = red[0];
        return;
    }
    if (bid >= 128) {                       // ---- x convert ----
        int vb = bid - 128;                 // 0..1023
        float4 w[4];
        #pragma unroll
        for (int j = 0; j < 4; j++) w[j] = xv[vb * 1024 + j * 256 + tid];
        #pragma unroll
        for (int j = 0; j < 4; j++) {
            int i = vb * 1024 + j * 256 + tid;
            __half2 a = __floats2half2_rn(w[j].x, w[j].y);
            __half2 b = __floats2half2_rn(w[j].z, w[j].w);
            ((uint2*)g_x16)[i] = make_uint2(h2u(a), h2u(b));
        }
        return;
    }

    // ---- gate MMA path (fp32-direct) ----
    const uint32_t sbase = smem_u32(sm);
    const int wid  = tid >> 5;
    const int lane = tid & 31;
    const int kc = bid & 7;
    const int kb = kc * 256;
    const int b0 = (bid >> 3) * 128;
    const int wm = (wid & 3) * 32;
    const int wn = (wid >> 2) * 32;

    float d[2][4][4];
    #pragma unroll
    for (int i = 0; i < 2; i++)
        #pragma unroll
        for (int j = 0; j < 4; j++)
            #pragma unroll
            for (int r = 0; r < 4; r++) d[i][j][r] = 0.0f;

    const int arow = tid >> 1;              // 0..127
    const int acol = (tid & 1) * 16;        // element col
    const int erow = tid >> 1;              // 0..63 (tid<128 only)

    float4 axr[4], exr[4];
    auto loadregs = [&](int c) {
        const int k0 = kb + c * 32;
        const float* ap = x + (size_t)(b0 + arow) * DM + k0 + acol;
        axr[0] = *(const float4*)(ap + 0);
        axr[1] = *(const float4*)(ap + 4);
        axr[2] = *(const float4*)(ap + 8);
        axr[3] = *(const float4*)(ap + 12);
        if (tid < 128) {
            const float* ep = enc + (size_t)erow * DM + k0 + acol;
            exr[0] = *(const float4*)(ep + 0);
            exr[1] = *(const float4*)(ep + 4);
            exr[2] = *(const float4*)(ep + 8);
            exr[3] = *(const float4*)(ep + 12);
        }
    };
    auto sts16 = [&](uint32_t baseoff, int row, int obyte, float4 f0, float4 f1) {
        __half2 h0 = __floats2half2_rn(f0.x, f0.y);
        __half2 h1 = __floats2half2_rn(f0.z, f0.w);
        __half2 h2 = __floats2half2_rn(f1.x, f1.y);
        __half2 h3 = __floats2half2_rn(f1.z, f1.w);
        uint32_t sw = baseoff + (uint32_t)row * 64 +
                      (uint32_t)(obyte ^ ((row & 6) << 3));
        *(uint4*)(sm + sw) = make_uint4(h2u(h0), h2u(h1), h2u(h2), h2u(h3));
    };

    const int a_row = wm + (lane & 15);
    const int a_kc  = (lane >> 4) * 16;
    const int b_row = wn + (lane & 7) + ((lane >> 4) << 3);
    const int b_kc  = ((lane >> 3) & 1) * 16;

    loadregs(0);

    for (int c = 0; c < 8; ++c) {
        sts16(0, arow, acol * 2,      axr[0], axr[1]);
        sts16(0, arow, acol * 2 + 16, axr[2], axr[3]);
        if (tid < 128) {
            sts16(8192, erow, acol * 2,      exr[0], exr[1]);
            sts16(8192, erow, acol * 2 + 16, exr[2], exr[3]);
        }
        __syncthreads();
        if (c < 7) loadregs(c + 1);

        #pragma unroll
        for (int k16 = 0; k16 < 2; ++k16) {
            const int koff = k16 * 32;
            uint32_t bh[2][4];
            #pragma unroll
            for (int q = 0; q < 2; ++q) {
                int row = b_row + q * 16;
                uint32_t sw = (uint32_t)row * 64 +
                              (uint32_t)((koff + b_kc) ^ ((row & 6) << 3));
                ldsm4(bh[q], sbase + 8192 + sw);
            }
            #pragma unroll
            for (int mb = 0; mb < 2; ++mb) {
                int row = a_row + mb * 16;
                uint32_t sw = (uint32_t)row * 64 +
                              (uint32_t)((koff + a_kc) ^ ((row & 6) << 3));
                uint32_t ah[4];
                ldsm4(ah, sbase + sw);
                #pragma unroll
                for (int q = 0; q < 2; ++q) {
                    mma_f16(d[mb][q*2],   ah, &bh[q][0]);
                    mma_f16(d[mb][q*2+1], ah, &bh[q][2]);
                }
            }
        }
        __syncthreads();
    }

    float* dst = g_gpart8 + (size_t)kc * (BATCH * NT);
    const int g = lane >> 2, t = lane & 3;
    #pragma unroll
    for (int mb = 0; mb < 2; ++mb) {
        #pragma unroll
        for (int half = 0; half < 2; ++half) {
            const int b = b0 + wm + mb * 16 + g + half * 8;
            #pragma unroll
            for (int nf = 0; nf < 4; ++nf) {
                const int col = wn + nf * 8 + t * 2;
                *(float2*)(dst + b * NT + col) =
                    make_float2(d[mb][nf][half*2+0], d[mb][nf][half*2+1]);
            }
        }
    }
}

// ---------------------------------------------------------------------------
// Launch 2: gate reduction over 8 chunks + bias + relu.
// ---------------------------------------------------------------------------
__global__ __launch_bounds__(256) void gate_reduce(
    const float* __restrict__ bias, float* __restrict__ gate)
{
    int idx = blockIdx.x * 256 + threadIdx.x;   // 0 .. 131071
    int n = idx & (NT - 1);
    float s = 0.0f;
    #pragma unroll
    for (int c = 0; c < 8; ++c) s += g_gpart8[(size_t)c * (BATCH * NT) + idx];
    float p = s - bias[n];
    gate[idx] = (p > 0.0f) ? p : 0.0f;
}

// ---------------------------------------------------------------------------
// Launch 3: GEMM1 (256 tiles, bid<256) + U transpose/norms (1024 blocks after).
// GEMM1: GVx[b,k] = gate * sum_d x16[b,d] * v16[k,d]. R10 proven shape:
// BM=BN=128, BK=32, 8 warps (4m x 2n), warp tile 32x64, double-buffered.
// SW64 swizzle on 64-byte rows: sw = row*64 + (kbyte ^ ((row&6)<<3)).
// ---------------------------------------------------------------------------
#define MMA_SMEM 32768

__global__ __launch_bounds__(256) void gemm1_prepu(
    const float* __restrict__ gate, const float* __restrict__ Uw)
{
    extern __shared__ char sm[];
    __shared__ float red[256];

    const int bid = blockIdx.x;
    const int tid = threadIdx.x;

    if (bid >= 256) {                      // ---- U transpose + norm partials ----
        int r  = bid - 256;                // 0..1023 = n*16 + dblk
        int n  = r >> 4;
        int d0 = (r & 15) * 128;
        float ss = 0.0f;
        #pragma unroll
        for (int it = 0; it < 4; it++) {
            int lin = tid + it * 256;
            int dl = lin >> 3;
            int q  = lin & 7;
            float4 w = *(const float4*)(Uw + ((size_t)n * DM + d0 + dl) * RK + q * 4);
            __half2 a = __floats2half2_rn(w.x, w.y);
            __half2 b = __floats2half2_rn(w.z, w.w);
            size_t o = (size_t)(d0 + dl) * DM + n * RK + q * 4;
            *(uint2*)(g_w16 + o) = make_uint2(h2u(a), h2u(b));
            ss += w.x*w.x + w.y*w.y + w.z*w.z + w.w*w.w;
        }
        red[tid] = ss;
        __syncthreads();
        for (int off = 128; off > 0; off >>= 1) {
            if (tid < off) red[tid] += red[tid + off];
            __syncthreads();
        }
        if (tid == 0) g_upart[r] = red[0];
        return;
    }

    // ---- GEMM1 tile ----
    const uint32_t sbase = smem_u32(sm);
    const int wid  = tid >> 5;
    const int lane = tid & 31;
    const int n0 = (bid & 15) * 128;
    const int b0 = (bid >> 4) * 128;
    const int wm = (wid & 3) * 32;
    const int wn = (wid >> 2) * 64;

    float d[2][8][4];
    #pragma unroll
    for (int i = 0; i < 2; i++)
        #pragma unroll
        for (int j = 0; j < 8; j++)
            #pragma unroll
            for (int r = 0; r < 4; r++) d[i][j][r] = 0.0f;

    const int r0c = tid >> 2;
    const int r1c = 64 + (tid >> 2);
    const int cbe = (tid & 3) * 8;
    const uint32_t sw0 = (uint32_t)r0c * 64 + (((tid & 3) * 16) ^ ((r0c & 6) << 3));
    const uint32_t sw1 = (uint32_t)r1c * 64 + (((tid & 3) * 16) ^ ((r1c & 6) << 3));

    auto issue = [&](int c) {
        const uint32_t st = sbase + (uint32_t)(c & 1) * 16384u;
        const int kb = c * 32;
        cp16(st + sw0,         g_x16 + (size_t)(b0 + r0c) * DM + kb + cbe);
        cp16(st + sw1,         g_x16 + (size_t)(b0 + r1c) * DM + kb + cbe);
        cp16(st + 8192 + sw0,  g_v16 + (size_t)(n0 + r0c) * DM + kb + cbe);
        cp16(st + 8192 + sw1,  g_v16 + (size_t)(n0 + r1c) * DM + kb + cbe);
        cp_commit();
    };

    const int a_row = wm + (lane & 15);
    const int a_kc  = (lane >> 4) * 16;
    const int b_row = wn + (lane & 7) + ((lane >> 4) << 3);
    const int b_kc  = ((lane >> 3) & 1) * 16;

    issue(0);

    for (int c = 0; c < 64; ++c) {
        if (c < 63) issue(c + 1);
        if (c < 63) cp_wait<1>(); else cp_wait<0>();
        __syncthreads();

        const uint32_t st = sbase + (uint32_t)(c & 1) * 16384u;

        #pragma unroll
        for (int k16 = 0; k16 < 2; ++k16) {
            const int koff = k16 * 32;
            uint32_t bh[4][4];
            #pragma unroll
            for (int q = 0; q < 4; ++q) {
                int row = b_row + q * 16;
                uint32_t sw = (uint32_t)row * 64 +
                              (uint32_t)((koff + b_kc) ^ ((row & 6) << 3));
                ldsm4(bh[q], st + 8192 + sw);
            }
            #pragma unroll
            for (int mb = 0; mb < 2; ++mb) {
                int row = a_row + mb * 16;
                uint32_t sw = (uint32_t)row * 64 +
                              (uint32_t)((koff + a_kc) ^ ((row & 6) << 3));
                uint32_t ah[4];
                ldsm4(ah, st + sw);
                #pragma unroll
                for (int q = 0; q < 4; ++q) {
                    mma_f16(d[mb][q*2],   ah, &bh[q][0]);
                    mma_f16(d[mb][q*2+1], ah, &bh[q][2]);
                }
            }
        }
        __syncthreads();
    }

    const int g = lane >> 2, t = lane & 3;
    #pragma unroll
    for (int mb = 0; mb < 2; ++mb) {
        #pragma unroll
        for (int half = 0; half < 2; ++half) {
            const int b = b0 + wm + mb * 16 + g + half * 8;
            #pragma unroll
            for (int ni = 0; ni < 8; ++ni) {
                const int colg = n0 + wn + ni * 8 + t * 2;
                const float gv = __ldg(&gate[b * NT + (colg >> 5)]);
                __half2 h2 = __floats2half2_rn(d[mb][ni][half*2+0] * gv,
                                               d[mb][ni][half*2+1] * gv);
                *(uint32_t*)(g_gv16 + (size_t)b * DM + colg) = *(const uint32_t*)&h2;
            }
        }
    }
}

// ---------------------------------------------------------------------------
// Launch 4: GEMM2 (out = GVx @ Wt) + frobenius folded into block (0,0).
// ---------------------------------------------------------------------------
__global__ __launch_bounds__(256) void gemm2_frob(
    float* __restrict__ outf, float* __restrict__ frob)
{
    extern __shared__ char sm[];
    const uint32_t sbase = smem_u32(sm);

    const int tid  = threadIdx.x;

    if (blockIdx.x == 0 && blockIdx.y == 0 && tid < NT) {
        int n = tid;
        float su = 0.0f, sv = 0.0f;
        #pragma unroll
        for (int j = 0; j < 16; j++) su += g_upart[n * 16 + j];
        #pragma unroll
        for (int j = 0; j < 16; j++) sv += g_vpart[n * 16 + j];
        frob[n] = sqrtf(su) * sqrtf(sv) * (1.0f / 256.0f);
    }

    const int wid  = tid >> 5;
    const int lane = tid & 31;
    const int n0 = blockIdx.x * 128;
    const int b0 = blockIdx.y * 128;
    const int wm = (wid & 3) * 32;
    const int wn = (wid >> 2) * 64;

    float d[2][8][4];
    #pragma unroll
    for (int i = 0; i < 2; i++)
        #pragma unroll
        for (int j = 0; j < 8; j++)
            #pragma unroll
            for (int r = 0; r < 4; r++) d[i][j][r] = 0.0f;

    const int r0c = tid >> 2;
    const int r1c = 64 + (tid >> 2);
    const int cbe = (tid & 3) * 8;
    const uint32_t sw0 = (uint32_t)r0c * 64 + (((tid & 3) * 16) ^ ((r0c & 6) << 3));
    const uint32_t sw1 = (uint32_t)r1c * 64 + (((tid & 3) * 16) ^ ((r1c & 6) << 3));

    auto issue = [&](int c) {
        const uint32_t st = sbase + (uint32_t)(c & 1) * 16384u;
        const int kb = c * 32;
        cp16(st + sw0,         g_gv16 + (size_t)(b0 + r0c) * DM + kb + cbe);
        cp16(st + sw1,         g_gv16 + (size_t)(b0 + r1c) * DM + kb + cbe);
        cp16(st + 8192 + sw0,  g_w16 + (size_t)(n0 + r0c) * DM + kb + cbe);
        cp16(st + 8192 + sw1,  g_w16 + (size_t)(n0 + r1c) * DM + kb + cbe);
        cp_commit();
    };

    const int a_row = wm + (lane & 15);
    const int a_kc  = (lane >> 4) * 16;
    const int b_row = wn + (lane & 7) + ((lane >> 4) << 3);
    const int b_kc  = ((lane >> 3) & 1) * 16;

    issue(0);

    for (int c = 0; c < 64; ++c) {
        if (c < 63) issue(c + 1);
        if (c < 63) cp_wait<1>(); else cp_wait<0>();
        __syncthreads();

        const uint32_t st = sbase + (uint32_t)(c & 1) * 16384u;

        #pragma unroll
        for (int k16 = 0; k16 < 2; ++k16) {
            const int koff = k16 * 32;
            uint32_t bh[4][4];
            #pragma unroll
            for (int q = 0; q < 4; ++q) {
                int row = b_row + q * 16;
                uint32_t sw = (uint32_t)row * 64 +
                              (uint32_t)((koff + b_kc) ^ ((row & 6) << 3));
                ldsm4(bh[q], st + 8192 + sw);
            }
            #pragma unroll
            for (int mb = 0; mb < 2; ++mb) {
                int row = a_row + mb * 16;
                uint32_t sw = (uint32_t)row * 64 +
                              (uint32_t)((koff + a_kc) ^ ((row & 6) << 3));
                uint32_t ah[4];
                ldsm4(ah, st + sw);
                #pragma unroll
                for (int q = 0; q < 4; ++q) {
                    mma_f16(d[mb][q*2],   ah, &bh[q][0]);
                    mma_f16(d[mb][q*2+1], ah, &bh[q][2]);
                }
            }
        }
        __syncthreads();
    }

    const int g = lane >> 2, t = lane & 3;
    #pragma unroll
    for (int mb = 0; mb < 2; ++mb) {
        #pragma unroll
        for (int half = 0; half < 2; ++half) {
            const int b = b0 + wm + mb * 16 + g + half * 8;
            #pragma unroll
            for (int ni = 0; ni < 8; ++ni) {
                const int colg = n0 + wn + ni * 8 + t * 2;
                *(float2*)(outf + (size_t)b * DM + colg) =
                    make_float2(d[mb][ni][half*2+0], d[mb][ni][half*2+1]);
            }
        }
    }
}

// ---------------------------------------------------------------------------
// d_out layout: [output 2048*2048 | gate 2048*64 | frob 64]
// ---------------------------------------------------------------------------
extern "C" void kernel_launch(void* const* d_in, const int* in_sizes, int n_in,
                              void* d_out, int out_size)
{
    const float* x    = (const float*)d_in[0];  // (2048, 2048)
    const float* Vw   = (const float*)d_in[1];  // (64, 32, 2048)
    const float* Uw   = (const float*)d_in[2];  // (64, 2048, 32)
    const float* enc  = (const float*)d_in[3];  // (64, 2048)
    const float* bias = (const float*)d_in[4];  // (64,)

    float* out  = (float*)d_out;
    float* gate = out + BATCH * DM;
    float* frob = gate + BATCH * NT;

    cudaFuncSetAttribute(gemm1_prepu, cudaFuncAttributeMaxDynamicSharedMemorySize, MMA_SMEM);
    cudaFuncSetAttribute(gemm2_frob, cudaFuncAttributeMaxDynamicSharedMemorySize, MMA_SMEM);

    gate_prep<<<2176, 256>>>(x, enc, (const float4*)x, (const float4*)Vw);
    gate_reduce<<<512, 256>>>(bias, gate);
    gemm1_prepu<<<1280, 256, MMA_SMEM>>>(gate, Uw);
    gemm2_frob<<<dim3(16, 16), 256, MMA_SMEM>>>(out, frob);
}

// round 16
// speedup vs baseline: 1.0465x; 1.0465x over previous
#include <cuda_runtime.h>
#include <cuda_fp16.h>
#include <cstdint>

#define DM 2048   // d_model
#define BATCH 2048
#define NT 64     // num transforms
#define RK 32     // rank

// ---------------------------------------------------------------------------
// Static device scratch (no allocation allowed). Single fp16 operand copies.
// ---------------------------------------------------------------------------
__device__ __half g_x16[BATCH * DM];    // x          [b][d]
__device__ __half g_v16[DM * DM];       // V_flat     [k][d]
__device__ __half g_w16[DM * DM];       // Wt = U^T   [d][k]
__device__ __half g_gv16[BATCH * DM];   // gated Vx   [b][k]
__device__ float g_vpart[1024];         // per-block sum-of-squares partials (V)
__device__ float g_upart[1024];         // per-block partials (U): [n*16 + dblk]
__device__ float g_gpart8[8 * BATCH * NT];  // gate split-K partials (4 MB)

// ---------------------------------------------------------------------------
// PTX helpers (portable sm_80 subset; ptxas here targets plain sm_103)
// ---------------------------------------------------------------------------
__device__ __forceinline__ uint32_t smem_u32(const void* p) {
    return (uint32_t)__cvta_generic_to_shared(p);
}
__device__ __forceinline__ void cp16(uint32_t dst, const void* src) {
    asm volatile("cp.async.cg.shared.global [%0], [%1], 16;\n" :: "r"(dst), "l"(src));
}
__device__ __forceinline__ void cp_commit() {
    asm volatile("cp.async.commit_group;\n" ::: "memory");
}
template<int N>
__device__ __forceinline__ void cp_wait() {
    asm volatile("cp.async.wait_group %0;\n" :: "n"(N) : "memory");
}
__device__ __forceinline__ void ldsm4(uint32_t* r, uint32_t addr) {
    asm volatile("ldmatrix.sync.aligned.m8n8.x4.shared.b16 {%0,%1,%2,%3}, [%4];"
                 : "=r"(r[0]), "=r"(r[1]), "=r"(r[2]), "=r"(r[3]) : "r"(addr));
}
__device__ __forceinline__ void mma_f16(float* d, const uint32_t* a, const uint32_t* b) {
    asm volatile(
        "mma.sync.aligned.m16n8k16.row.col.f32.f16.f16.f32 "
        "{%0,%1,%2,%3}, {%4,%5,%6,%7}, {%8,%9}, {%0,%1,%2,%3};"
        : "+f"(d[0]), "+f"(d[1]), "+f"(d[2]), "+f"(d[3])
        : "r"(a[0]), "r"(a[1]), "r"(a[2]), "r"(a[3]), "r"(b[0]), "r"(b[1]));
}
__device__ __forceinline__ uint32_t h2u(__half2 h) { return *(uint32_t*)&h; }

// ---------------------------------------------------------------------------
// Launch 1 (merged): gate-from-fp32 [0,128) + x convert [128,1152)
//                    + V convert/norms [1152,2176).
// Gate: partial[kc][b][n] = sum_{k in 256-chunk} fp16(x)[b,k]*fp16(enc)[n,k]
//   BM=128, BN=64, Kchunk=256 (8 k-tiles of 32). kc = bid&7, b0 = (bid>>3)*128.
//   Loads fp32, converts in regs, STS into the SAME swizzled fp16 layout the
//   cp.async path produced -> bit-identical gate values.
// Converts: 4 float4 per thread (MLP=4) so 2 CTA/SM occupancy still saturates.
// ---------------------------------------------------------------------------
__global__ __launch_bounds__(256) void gate_prep(
    const float* __restrict__ x, const float* __restrict__ enc,
    const float4* __restrict__ xv, const float4* __restrict__ v)
{
    __shared__ __align__(1024) char sm[12288];   // A 8K | E 4K (single stage)
    __shared__ float red[256];

    const int bid = blockIdx.x;
    const int tid = threadIdx.x;

    if (bid >= 1152) {                      // ---- V + norm partials ----
        int vb = bid - 1152;                // 0..1023
        float4 w[4];
        #pragma unroll
        for (int j = 0; j < 4; j++) w[j] = v[vb * 1024 + j * 256 + tid];
        float s = 0.0f;
        #pragma unroll
        for (int j = 0; j < 4; j++) {
            int i = vb * 1024 + j * 256 + tid;
            __half2 a = __floats2half2_rn(w[j].x, w[j].y);
            __half2 b = __floats2half2_rn(w[j].z, w[j].w);
            ((uint2*)g_v16)[i] = make_uint2(h2u(a), h2u(b));
            s += w[j].x*w[j].x + w[j].y*w[j].y + w[j].z*w[j].z + w[j].w*w[j].w;
        }
        red[tid] = s;
        __syncthreads();
        for (int off = 128; off > 0; off >>= 1) {
            if (tid < off) red[tid] += red[tid + off];
            __syncthreads();
        }
        if (tid == 0) g_vpart[vb] = red[0];
        return;
    }
    if (bid >= 128) {                       // ---- x convert ----
        int vb = bid - 128;                 // 0..1023
        float4 w[4];
        #pragma unroll
        for (int j = 0; j < 4; j++) w[j] = xv[vb * 1024 + j * 256 + tid];
        #pragma unroll
        for (int j = 0; j < 4; j++) {
            int i = vb * 1024 + j * 256 + tid;
            __half2 a = __floats2half2_rn(w[j].x, w[j].y);
            __half2 b = __floats2half2_rn(w[j].z, w[j].w);
            ((uint2*)g_x16)[i] = make_uint2(h2u(a), h2u(b));
        }
        return;
    }

    // ---- gate MMA path (fp32-direct) ----
    const uint32_t sbase = smem_u32(sm);
    const int wid  = tid >> 5;
    const int lane = tid & 31;
    const int kc = bid & 7;
    const int kb = kc * 256;
    const int b0 = (bid >> 3) * 128;
    const int wm = (wid & 3) * 32;
    const int wn = (wid >> 2) * 32;

    float d[2][4][4];
    #pragma unroll
    for (int i = 0; i < 2; i++)
        #pragma unroll
        for (int j = 0; j < 4; j++)
            #pragma unroll
            for (int r = 0; r < 4; r++) d[i][j][r] = 0.0f;

    // per-thread load/STS coords: A 128 rows x 32 cols (2 thr/row, 16 cols each)
    const int arow = tid >> 1;              // 0..127
    const int acol = (tid & 1) * 16;        // element col
    const int erow = tid >> 1;              // 0..63 (tid<128 only)

    float4 axr[4], exr[4];
    auto loadregs = [&](int c) {
        const int k0 = kb + c * 32;
        const float* ap = x + (size_t)(b0 + arow) * DM + k0 + acol;
        axr[0] = *(const float4*)(ap + 0);
        axr[1] = *(const float4*)(ap + 4);
        axr[2] = *(const float4*)(ap + 8);
        axr[3] = *(const float4*)(ap + 12);
        if (tid < 128) {
            const float* ep = enc + (size_t)erow * DM + k0 + acol;
            exr[0] = *(const float4*)(ep + 0);
            exr[1] = *(const float4*)(ep + 4);
            exr[2] = *(const float4*)(ep + 8);
            exr[3] = *(const float4*)(ep + 12);
        }
    };
    auto sts16 = [&](uint32_t baseoff, int row, int obyte, float4 f0, float4 f1) {
        __half2 h0 = __floats2half2_rn(f0.x, f0.y);
        __half2 h1 = __floats2half2_rn(f0.z, f0.w);
        __half2 h2 = __floats2half2_rn(f1.x, f1.y);
        __half2 h3 = __floats2half2_rn(f1.z, f1.w);
        uint32_t sw = baseoff + (uint32_t)row * 64 +
                      (uint32_t)(obyte ^ ((row & 6) << 3));
        *(uint4*)(sm + sw) = make_uint4(h2u(h0), h2u(h1), h2u(h2), h2u(h3));
    };

    const int a_row = wm + (lane & 15);
    const int a_kc  = (lane >> 4) * 16;
    const int b_row = wn + (lane & 7) + ((lane >> 4) << 3);
    const int b_kc  = ((lane >> 3) & 1) * 16;

    loadregs(0);

    for (int c = 0; c < 8; ++c) {
        // STS stage (single buffer; bytes identical to the cp.async layout)
        sts16(0, arow, acol * 2,      axr[0], axr[1]);
        sts16(0, arow, acol * 2 + 16, axr[2], axr[3]);
        if (tid < 128) {
            sts16(8192, erow, acol * 2,      exr[0], exr[1]);
            sts16(8192, erow, acol * 2 + 16, exr[2], exr[3]);
        }
        __syncthreads();
        if (c < 7) loadregs(c + 1);   // prefetch next chunk, overlap with MMA

        #pragma unroll
        for (int k16 = 0; k16 < 2; ++k16) {
            const int koff = k16 * 32;
            uint32_t bh[2][4];
            #pragma unroll
            for (int q = 0; q < 2; ++q) {
                int row = b_row + q * 16;
                uint32_t sw = (uint32_t)row * 64 +
                              (uint32_t)((koff + b_kc) ^ ((row & 6) << 3));
                ldsm4(bh[q], sbase + 8192 + sw);
            }
            #pragma unroll
            for (int mb = 0; mb < 2; ++mb) {
                int row = a_row + mb * 16;
                uint32_t sw = (uint32_t)row * 64 +
                              (uint32_t)((koff + a_kc) ^ ((row & 6) << 3));
                uint32_t ah[4];
                ldsm4(ah, sbase + sw);
                #pragma unroll
                for (int q = 0; q < 2; ++q) {
                    mma_f16(d[mb][q*2],   ah, &bh[q][0]);
                    mma_f16(d[mb][q*2+1], ah, &bh[q][2]);
                }
            }
        }
        __syncthreads();   // stage reuse guard
    }

    float* dst = g_gpart8 + (size_t)kc * (BATCH * NT);
    const int g = lane >> 2, t = lane & 3;
    #pragma unroll
    for (int mb = 0; mb < 2; ++mb) {
        #pragma unroll
        for (int half = 0; half < 2; ++half) {
            const int b = b0 + wm + mb * 16 + g + half * 8;
            #pragma unroll
            for (int nf = 0; nf < 4; ++nf) {
                const int col = wn + nf * 8 + t * 2;
                *(float2*)(dst + b * NT + col) =
                    make_float2(d[mb][nf][half*2+0], d[mb][nf][half*2+1]);
            }
        }
    }
}

// ---------------------------------------------------------------------------
// Launch 2: gate reduction over 8 chunks + bias + relu.
// ---------------------------------------------------------------------------
__global__ __launch_bounds__(256) void gate_reduce(
    const float* __restrict__ bias, float* __restrict__ gate)
{
    int idx = blockIdx.x * 256 + threadIdx.x;   // 0 .. 131071
    int n = idx & (NT - 1);
    float s = 0.0f;
    #pragma unroll
    for (int c = 0; c < 8; ++c) s += g_gpart8[(size_t)c * (BATCH * NT) + idx];
    float p = s - bias[n];
    gate[idx] = (p > 0.0f) ? p : 0.0f;
}

// ---------------------------------------------------------------------------
// Launch 3: GEMM1 (256 tiles, bid<256) + U transpose/norms (1024 blocks after).
// GEMM1: GVx[b,k] = gate * sum_d x16[b,d] * v16[k,d]. R10 proven shape:
// BM=BN=128, BK=32, 8 warps (4m x 2n), warp tile 32x64, double-buffered.
// SW64 swizzle on 64-byte rows: sw = row*64 + (kbyte ^ ((row&6)<<3)).
// ---------------------------------------------------------------------------
#define MMA_SMEM 32768

__global__ __launch_bounds__(256) void gemm1_prepu(
    const float* __restrict__ gate, const float* __restrict__ Uw)
{
    extern __shared__ char sm[];
    __shared__ float red[256];

    const int bid = blockIdx.x;
    const int tid = threadIdx.x;

    if (bid >= 256) {                      // ---- U transpose + norm partials ----
        int r  = bid - 256;                // 0..1023 = n*16 + dblk
        int n  = r >> 4;
        int d0 = (r & 15) * 128;
        float ss = 0.0f;
        #pragma unroll
        for (int it = 0; it < 4; it++) {
            int lin = tid + it * 256;
            int dl = lin >> 3;
            int q  = lin & 7;
            float4 w = *(const float4*)(Uw + ((size_t)n * DM + d0 + dl) * RK + q * 4);
            __half2 a = __floats2half2_rn(w.x, w.y);
            __half2 b = __floats2half2_rn(w.z, w.w);
            size_t o = (size_t)(d0 + dl) * DM + n * RK + q * 4;
            *(uint2*)(g_w16 + o) = make_uint2(h2u(a), h2u(b));
            ss += w.x*w.x + w.y*w.y + w.z*w.z + w.w*w.w;
        }
        red[tid] = ss;
        __syncthreads();
        for (int off = 128; off > 0; off >>= 1) {
            if (tid < off) red[tid] += red[tid + off];
            __syncthreads();
        }
        if (tid == 0) g_upart[r] = red[0];
        return;
    }

    // ---- GEMM1 tile ----
    const uint32_t sbase = smem_u32(sm);
    const int wid  = tid >> 5;
    const int lane = tid & 31;
    const int n0 = (bid & 15) * 128;
    const int b0 = (bid >> 4) * 128;
    const int wm = (wid & 3) * 32;
    const int wn = (wid >> 2) * 64;

    float d[2][8][4];
    #pragma unroll
    for (int i = 0; i < 2; i++)
        #pragma unroll
        for (int j = 0; j < 8; j++)
            #pragma unroll
            for (int r = 0; r < 4; r++) d[i][j][r] = 0.0f;

    const int r0c = tid >> 2;
    const int r1c = 64 + (tid >> 2);
    const int cbe = (tid & 3) * 8;
    const uint32_t sw0 = (uint32_t)r0c * 64 + (((tid & 3) * 16) ^ ((r0c & 6) << 3));
    const uint32_t sw1 = (uint32_t)r1c * 64 + (((tid & 3) * 16) ^ ((r1c & 6) << 3));

    auto issue = [&](int c) {
        const uint32_t st = sbase + (uint32_t)(c & 1) * 16384u;
        const int kb = c * 32;
        cp16(st + sw0,         g_x16 + (size_t)(b0 + r0c) * DM + kb + cbe);
        cp16(st + sw1,         g_x16 + (size_t)(b0 + r1c) * DM + kb + cbe);
        cp16(st + 8192 + sw0,  g_v16 + (size_t)(n0 + r0c) * DM + kb + cbe);
        cp16(st + 8192 + sw1,  g_v16 + (size_t)(n0 + r1c) * DM + kb + cbe);
        cp_commit();
    };

    const int a_row = wm + (lane & 15);
    const int a_kc  = (lane >> 4) * 16;
    const int b_row = wn + (lane & 7) + ((lane >> 4) << 3);
    const int b_kc  = ((lane >> 3) & 1) * 16;

    issue(0);

    for (int c = 0; c < 64; ++c) {
        if (c < 63) issue(c + 1);
        if (c < 63) cp_wait<1>(); else cp_wait<0>();
        __syncthreads();

        const uint32_t st = sbase + (uint32_t)(c & 1) * 16384u;

        #pragma unroll
        for (int k16 = 0; k16 < 2; ++k16) {
            const int koff = k16 * 32;
            uint32_t bh[4][4];
            #pragma unroll
            for (int q = 0; q < 4; ++q) {
                int row = b_row + q * 16;
                uint32_t sw = (uint32_t)row * 64 +
                              (uint32_t)((koff + b_kc) ^ ((row & 6) << 3));
                ldsm4(bh[q], st + 8192 + sw);
            }
            #pragma unroll
            for (int mb = 0; mb < 2; ++mb) {
                int row = a_row + mb * 16;
                uint32_t sw = (uint32_t)row * 64 +
                              (uint32_t)((koff + a_kc) ^ ((row & 6) << 3));
                uint32_t ah[4];
                ldsm4(ah, st + sw);
                #pragma unroll
                for (int q = 0; q < 4; ++q) {
                    mma_f16(d[mb][q*2],   ah, &bh[q][0]);
                    mma_f16(d[mb][q*2+1], ah, &bh[q][2]);
                }
            }
        }
        __syncthreads();
    }

    const int g = lane >> 2, t = lane & 3;
    #pragma unroll
    for (int mb = 0; mb < 2; ++mb) {
        #pragma unroll
        for (int half = 0; half < 2; ++half) {
            const int b = b0 + wm + mb * 16 + g + half * 8;
            #pragma unroll
            for (int ni = 0; ni < 8; ++ni) {
                const int colg = n0 + wn + ni * 8 + t * 2;
                const float gv = __ldg(&gate[b * NT + (colg >> 5)]);
                __half2 h2 = __floats2half2_rn(d[mb][ni][half*2+0] * gv,
                                               d[mb][ni][half*2+1] * gv);
                *(uint32_t*)(g_gv16 + (size_t)b * DM + colg) = *(const uint32_t*)&h2;
            }
        }
    }
}

// ---------------------------------------------------------------------------
// Launch 4: GEMM2 (out = GVx @ Wt) + frobenius folded into block (0,0).
// ---------------------------------------------------------------------------
__global__ __launch_bounds__(256) void gemm2_frob(
    float* __restrict__ outf, float* __restrict__ frob)
{
    extern __shared__ char sm[];
    const uint32_t sbase = smem_u32(sm);

    const int tid  = threadIdx.x;

    if (blockIdx.x == 0 && blockIdx.y == 0 && tid < NT) {
        int n = tid;
        float su = 0.0f, sv = 0.0f;
        #pragma unroll
        for (int j = 0; j < 16; j++) su += g_upart[n * 16 + j];
        #pragma unroll
        for (int j = 0; j < 16; j++) sv += g_vpart[n * 16 + j];
        frob[n] = sqrtf(su) * sqrtf(sv) * (1.0f / 256.0f);
    }

    const int wid  = tid >> 5;
    const int lane = tid & 31;
    const int n0 = blockIdx.x * 128;
    const int b0 = blockIdx.y * 128;
    const int wm = (wid & 3) * 32;
    const int wn = (wid >> 2) * 64;

    float d[2][8][4];
    #pragma unroll
    for (int i = 0; i < 2; i++)
        #pragma unroll
        for (int j = 0; j < 8; j++)
            #pragma unroll
            for (int r = 0; r < 4; r++) d[i][j][r] = 0.0f;

    const int r0c = tid >> 2;
    const int r1c = 64 + (tid >> 2);
    const int cbe = (tid & 3) * 8;
    const uint32_t sw0 = (uint32_t)r0c * 64 + (((tid & 3) * 16) ^ ((r0c & 6) << 3));
    const uint32_t sw1 = (uint32_t)r1c * 64 + (((tid & 3) * 16) ^ ((r1c & 6) << 3));

    auto issue = [&](int c) {
        const uint32_t st = sbase + (uint32_t)(c & 1) * 16384u;
        const int kb = c * 32;
        cp16(st + sw0,         g_gv16 + (size_t)(b0 + r0c) * DM + kb + cbe);
        cp16(st + sw1,         g_gv16 + (size_t)(b0 + r1c) * DM + kb + cbe);
        cp16(st + 8192 + sw0,  g_w16 + (size_t)(n0 + r0c) * DM + kb + cbe);
        cp16(st + 8192 + sw1,  g_w16 + (size_t)(n0 + r1c) * DM + kb + cbe);
        cp_commit();
    };

    const int a_row = wm + (lane & 15);
    const int a_kc  = (lane >> 4) * 16;
    const int b_row = wn + (lane & 7) + ((lane >> 4) << 3);
    const int b_kc  = ((lane >> 3) & 1) * 16;

    issue(0);

    for (int c = 0; c < 64; ++c) {
        if (c < 63) issue(c + 1);
        if (c < 63) cp_wait<1>(); else cp_wait<0>();
        __syncthreads();

        const uint32_t st = sbase + (uint32_t)(c & 1) * 16384u;

        #pragma unroll
        for (int k16 = 0; k16 < 2; ++k16) {
            const int koff = k16 * 32;
            uint32_t bh[4][4];
            #pragma unroll
            for (int q = 0; q < 4; ++q) {
                int row = b_row + q * 16;
                uint32_t sw = (uint32_t)row * 64 +
                              (uint32_t)((koff + b_kc) ^ ((row & 6) << 3));
                ldsm4(bh[q], st + 8192 + sw);
            }
            #pragma unroll
            for (int mb = 0; mb < 2; ++mb) {
                int row = a_row + mb * 16;
                uint32_t sw = (uint32_t)row * 64 +
                              (uint32_t)((koff + a_kc) ^ ((row & 6) << 3));
                uint32_t ah[4];
                ldsm4(ah, st + sw);
                #pragma unroll
                for (int q = 0; q < 4; ++q) {
                    mma_f16(d[mb][q*2],   ah, &bh[q][0]);
                    mma_f16(d[mb][q*2+1], ah, &bh[q][2]);
                }
            }
        }
        __syncthreads();
    }

    const int g = lane >> 2, t = lane & 3;
    #pragma unroll
    for (int mb = 0; mb < 2; ++mb) {
        #pragma unroll
        for (int half = 0; half < 2; ++half) {
            const int b = b0 + wm + mb * 16 + g + half * 8;
            #pragma unroll
            for (int ni = 0; ni < 8; ++ni) {
                const int colg = n0 + wn + ni * 8 + t * 2;
                *(float2*)(outf + (size_t)b * DM + colg) =
                    make_float2(d[mb][ni][half*2+0], d[mb][ni][half*2+1]);
            }
        }
    }
}

// ---------------------------------------------------------------------------
// d_out layout: [output 2048*2048 | gate 2048*64 | frob 64]
// ---------------------------------------------------------------------------
extern "C" void kernel_launch(void* const* d_in, const int* in_sizes, int n_in,
                              void* d_out, int out_size)
{
    const float* x    = (const float*)d_in[0];  // (2048, 2048)
    const float* Vw   = (const float*)d_in[1];  // (64, 32, 2048)
    const float* Uw   = (const float*)d_in[2];  // (64, 2048, 32)
    const float* enc  = (const float*)d_in[3];  // (64, 2048)
    const float* bias = (const float*)d_in[4];  // (64,)

    float* out  = (float*)d_out;
    float* gate = out + BATCH * DM;
    float* frob = gate + BATCH * NT;

    cudaFuncSetAttribute(gemm1_prepu, cudaFuncAttributeMaxDynamicSharedMemorySize, MMA_SMEM);
    cudaFuncSetAttribute(gemm2_frob, cudaFuncAttributeMaxDynamicSharedMemorySize, MMA_SMEM);

    gate_prep<<<2176, 256>>>(x, enc, (const float4*)x, (const float4*)Vw);
    gate_reduce<<<512, 256>>>(bias, gate);
    gemm1_prepu<<<1280, 256, MMA_SMEM>>>(gate, Uw);
    gemm2_frob<<<dim3(16, 16), 256, MMA_SMEM>>>(out, frob);
}

// round 17
// speedup vs baseline: 1.0599x; 1.0128x over previous
#include <cuda_runtime.h>
#include <cuda_fp16.h>
#include <cstdint>

#define DM 2048   // d_model
#define BATCH 2048
#define NT 64     // num transforms
#define RK 32     // rank

// ---------------------------------------------------------------------------
// Static device scratch (no allocation allowed). Single fp16 operand copies.
// ---------------------------------------------------------------------------
__device__ __half g_x16[BATCH * DM];    // x          [b][d]
__device__ __half g_v16[DM * DM];       // V_flat     [k][d]
__device__ __half g_w16[DM * DM];       // Wt = U^T   [d][k]
__device__ __half g_gv16[BATCH * DM];   // gated Vx   [b][k]
__device__ float g_vpart[512];          // per-block sum-of-squares partials (V)
__device__ float g_upart[1024];         // per-block partials (U): [n*16 + dblk]
__device__ float g_gpart8[8 * BATCH * NT];  // gate split-K partials (4 MB)

// ---------------------------------------------------------------------------
// PTX helpers (portable sm_80 subset; ptxas here targets plain sm_103)
// ---------------------------------------------------------------------------
__device__ __forceinline__ uint32_t smem_u32(const void* p) {
    return (uint32_t)__cvta_generic_to_shared(p);
}
__device__ __forceinline__ void cp16(uint32_t dst, const void* src) {
    asm volatile("cp.async.cg.shared.global [%0], [%1], 16;\n" :: "r"(dst), "l"(src));
}
__device__ __forceinline__ void cp_commit() {
    asm volatile("cp.async.commit_group;\n" ::: "memory");
}
template<int N>
__device__ __forceinline__ void cp_wait() {
    asm volatile("cp.async.wait_group %0;\n" :: "n"(N) : "memory");
}
__device__ __forceinline__ void ldsm4(uint32_t* r, uint32_t addr) {
    asm volatile("ldmatrix.sync.aligned.m8n8.x4.shared.b16 {%0,%1,%2,%3}, [%4];"
                 : "=r"(r[0]), "=r"(r[1]), "=r"(r[2]), "=r"(r[3]) : "r"(addr));
}
__device__ __forceinline__ void mma_f16(float* d, const uint32_t* a, const uint32_t* b) {
    asm volatile(
        "mma.sync.aligned.m16n8k16.row.col.f32.f16.f16.f32 "
        "{%0,%1,%2,%3}, {%4,%5,%6,%7}, {%8,%9}, {%0,%1,%2,%3};"
        : "+f"(d[0]), "+f"(d[1]), "+f"(d[2]), "+f"(d[3])
        : "r"(a[0]), "r"(a[1]), "r"(a[2]), "r"(a[3]), "r"(b[0]), "r"(b[1]));
}
__device__ __forceinline__ uint32_t h2u(__half2 h) { return *(uint32_t*)&h; }

// ---------------------------------------------------------------------------
// Launch 1 (merged): gate-from-fp32 [0,128) + x convert [128,640)
//                    + V convert/norms [640,1152).
// Convert branches now use 8 independent float4 per thread (MLP=8) so the
// latency-bound loops expose half the DRAM latency (R15 showed occupancy
// hints poison the shared register allocation; MLP is the orthogonal lever).
// Gate MMA branch: byte-identical to R13/R16 (bit-identical gate values).
// ---------------------------------------------------------------------------
__global__ __launch_bounds__(256) void gate_prep(
    const float* __restrict__ x, const float* __restrict__ enc,
    const float4* __restrict__ xv, const float4* __restrict__ v)
{
    __shared__ __align__(1024) char sm[12288];   // A 8K | E 4K (single stage)
    __shared__ float red[256];

    const int bid = blockIdx.x;
    const int tid = threadIdx.x;

    if (bid >= 640) {                       // ---- V + norm partials (MLP=8) ----
        int vb = bid - 640;                 // 0..511, 2048 float4 per block
        float4 w[8];
        #pragma unroll
        for (int j = 0; j < 8; j++) w[j] = v[vb * 2048 + j * 256 + tid];
        float s = 0.0f;
        #pragma unroll
        for (int j = 0; j < 8; j++) {
            int i = vb * 2048 + j * 256 + tid;
            __half2 a = __floats2half2_rn(w[j].x, w[j].y);
            __half2 b = __floats2half2_rn(w[j].z, w[j].w);
            ((uint2*)g_v16)[i] = make_uint2(h2u(a), h2u(b));
            s += w[j].x*w[j].x + w[j].y*w[j].y + w[j].z*w[j].z + w[j].w*w[j].w;
        }
        red[tid] = s;
        __syncthreads();
        for (int off = 128; off > 0; off >>= 1) {
            if (tid < off) red[tid] += red[tid + off];
            __syncthreads();
        }
        if (tid == 0) g_vpart[vb] = red[0];
        return;
    }
    if (bid >= 128) {                       // ---- x convert (MLP=8) ----
        int vb = bid - 128;                 // 0..511
        float4 w[8];
        #pragma unroll
        for (int j = 0; j < 8; j++) w[j] = xv[vb * 2048 + j * 256 + tid];
        #pragma unroll
        for (int j = 0; j < 8; j++) {
            int i = vb * 2048 + j * 256 + tid;
            __half2 a = __floats2half2_rn(w[j].x, w[j].y);
            __half2 b = __floats2half2_rn(w[j].z, w[j].w);
            ((uint2*)g_x16)[i] = make_uint2(h2u(a), h2u(b));
        }
        return;
    }

    // ---- gate MMA path (fp32-direct) — identical to R13/R16 ----
    const uint32_t sbase = smem_u32(sm);
    const int wid  = tid >> 5;
    const int lane = tid & 31;
    const int kc = bid & 7;
    const int kb = kc * 256;
    const int b0 = (bid >> 3) * 128;
    const int wm = (wid & 3) * 32;
    const int wn = (wid >> 2) * 32;

    float d[2][4][4];
    #pragma unroll
    for (int i = 0; i < 2; i++)
        #pragma unroll
        for (int j = 0; j < 4; j++)
            #pragma unroll
            for (int r = 0; r < 4; r++) d[i][j][r] = 0.0f;

    const int arow = tid >> 1;              // 0..127
    const int acol = (tid & 1) * 16;        // element col
    const int erow = tid >> 1;              // 0..63 (tid<128 only)

    float4 axr[4], exr[4];
    auto loadregs = [&](int c) {
        const int k0 = kb + c * 32;
        const float* ap = x + (size_t)(b0 + arow) * DM + k0 + acol;
        axr[0] = *(const float4*)(ap + 0);
        axr[1] = *(const float4*)(ap + 4);
        axr[2] = *(const float4*)(ap + 8);
        axr[3] = *(const float4*)(ap + 12);
        if (tid < 128) {
            const float* ep = enc + (size_t)erow * DM + k0 + acol;
            exr[0] = *(const float4*)(ep + 0);
            exr[1] = *(const float4*)(ep + 4);
            exr[2] = *(const float4*)(ep + 8);
            exr[3] = *(const float4*)(ep + 12);
        }
    };
    auto sts16 = [&](uint32_t baseoff, int row, int obyte, float4 f0, float4 f1) {
        __half2 h0 = __floats2half2_rn(f0.x, f0.y);
        __half2 h1 = __floats2half2_rn(f0.z, f0.w);
        __half2 h2 = __floats2half2_rn(f1.x, f1.y);
        __half2 h3 = __floats2half2_rn(f1.z, f1.w);
        uint32_t sw = baseoff + (uint32_t)row * 64 +
                      (uint32_t)(obyte ^ ((row & 6) << 3));
        *(uint4*)(sm + sw) = make_uint4(h2u(h0), h2u(h1), h2u(h2), h2u(h3));
    };

    const int a_row = wm + (lane & 15);
    const int a_kc  = (lane >> 4) * 16;
    const int b_row = wn + (lane & 7) + ((lane >> 4) << 3);
    const int b_kc  = ((lane >> 3) & 1) * 16;

    loadregs(0);

    for (int c = 0; c < 8; ++c) {
        sts16(0, arow, acol * 2,      axr[0], axr[1]);
        sts16(0, arow, acol * 2 + 16, axr[2], axr[3]);
        if (tid < 128) {
            sts16(8192, erow, acol * 2,      exr[0], exr[1]);
            sts16(8192, erow, acol * 2 + 16, exr[2], exr[3]);
        }
        __syncthreads();
        if (c < 7) loadregs(c + 1);

        #pragma unroll
        for (int k16 = 0; k16 < 2; ++k16) {
            const int koff = k16 * 32;
            uint32_t bh[2][4];
            #pragma unroll
            for (int q = 0; q < 2; ++q) {
                int row = b_row + q * 16;
                uint32_t sw = (uint32_t)row * 64 +
                              (uint32_t)((koff + b_kc) ^ ((row & 6) << 3));
                ldsm4(bh[q], sbase + 8192 + sw);
            }
            #pragma unroll
            for (int mb = 0; mb < 2; ++mb) {
                int row = a_row + mb * 16;
                uint32_t sw = (uint32_t)row * 64 +
                              (uint32_t)((koff + a_kc) ^ ((row & 6) << 3));
                uint32_t ah[4];
                ldsm4(ah, sbase + sw);
                #pragma unroll
                for (int q = 0; q < 2; ++q) {
                    mma_f16(d[mb][q*2],   ah, &bh[q][0]);
                    mma_f16(d[mb][q*2+1], ah, &bh[q][2]);
                }
            }
        }
        __syncthreads();
    }

    float* dst = g_gpart8 + (size_t)kc * (BATCH * NT);
    const int g = lane >> 2, t = lane & 3;
    #pragma unroll
    for (int mb = 0; mb < 2; ++mb) {
        #pragma unroll
        for (int half = 0; half < 2; ++half) {
            const int b = b0 + wm + mb * 16 + g + half * 8;
            #pragma unroll
            for (int nf = 0; nf < 4; ++nf) {
                const int col = wn + nf * 8 + t * 2;
                *(float2*)(dst + b * NT + col) =
                    make_float2(d[mb][nf][half*2+0], d[mb][nf][half*2+1]);
            }
        }
    }
}

// ---------------------------------------------------------------------------
// Launch 2: gate reduction, vectorized x4 (float4 loads; same per-element
// c = 0..7 sum order -> gate bit-identical to R16). 128 blocks.
// ---------------------------------------------------------------------------
__global__ __launch_bounds__(256) void gate_reduce(
    const float* __restrict__ bias, float* __restrict__ gate)
{
    int idx4 = (blockIdx.x * 256 + threadIdx.x) * 4;   // 0 .. 131068, step 4
    int n = idx4 & (NT - 1);                           // multiple of 4, <= 60
    float4 s = make_float4(0.f, 0.f, 0.f, 0.f);
    #pragma unroll
    for (int c = 0; c < 8; ++c) {
        float4 p = *(const float4*)(g_gpart8 + (size_t)c * (BATCH * NT) + idx4);
        s.x += p.x; s.y += p.y; s.z += p.z; s.w += p.w;
    }
    float4 bv = *(const float4*)(bias + n);
    float4 o;
    o.x = s.x - bv.x; o.x = (o.x > 0.f) ? o.x : 0.f;
    o.y = s.y - bv.y; o.y = (o.y > 0.f) ? o.y : 0.f;
    o.z = s.z - bv.z; o.z = (o.z > 0.f) ? o.z : 0.f;
    o.w = s.w - bv.w; o.w = (o.w > 0.f) ? o.w : 0.f;
    *(float4*)(gate + idx4) = o;
}

// ---------------------------------------------------------------------------
// Launch 3: GEMM1 (256 tiles, bid<256) + U transpose/norms (1024 blocks after).
// Byte-identical to R13/R16.
// ---------------------------------------------------------------------------
#define MMA_SMEM 32768

__global__ __launch_bounds__(256) void gemm1_prepu(
    const float* __restrict__ gate, const float* __restrict__ Uw)
{
    extern __shared__ char sm[];
    __shared__ float red[256];

    const int bid = blockIdx.x;
    const int tid = threadIdx.x;

    if (bid >= 256) {                      // ---- U transpose + norm partials ----
        int r  = bid - 256;                // 0..1023 = n*16 + dblk
        int n  = r >> 4;
        int d0 = (r & 15) * 128;
        float ss = 0.0f;
        #pragma unroll
        for (int it = 0; it < 4; it++) {
            int lin = tid + it * 256;
            int dl = lin >> 3;
            int q  = lin & 7;
            float4 w = *(const float4*)(Uw + ((size_t)n * DM + d0 + dl) * RK + q * 4);
            __half2 a = __floats2half2_rn(w.x, w.y);
            __half2 b = __floats2half2_rn(w.z, w.w);
            size_t o = (size_t)(d0 + dl) * DM + n * RK + q * 4;
            *(uint2*)(g_w16 + o) = make_uint2(h2u(a), h2u(b));
            ss += w.x*w.x + w.y*w.y + w.z*w.z + w.w*w.w;
        }
        red[tid] = ss;
        __syncthreads();
        for (int off = 128; off > 0; off >>= 1) {
            if (tid < off) red[tid] += red[tid + off];
            __syncthreads();
        }
        if (tid == 0) g_upart[r] = red[0];
        return;
    }

    // ---- GEMM1 tile ----
    const uint32_t sbase = smem_u32(sm);
    const int wid  = tid >> 5;
    const int lane = tid & 31;
    const int n0 = (bid & 15) * 128;
    const int b0 = (bid >> 4) * 128;
    const int wm = (wid & 3) * 32;
    const int wn = (wid >> 2) * 64;

    float d[2][8][4];
    #pragma unroll
    for (int i = 0; i < 2; i++)
        #pragma unroll
        for (int j = 0; j < 8; j++)
            #pragma unroll
            for (int r = 0; r < 4; r++) d[i][j][r] = 0.0f;

    const int r0c = tid >> 2;
    const int r1c = 64 + (tid >> 2);
    const int cbe = (tid & 3) * 8;
    const uint32_t sw0 = (uint32_t)r0c * 64 + (((tid & 3) * 16) ^ ((r0c & 6) << 3));
    const uint32_t sw1 = (uint32_t)r1c * 64 + (((tid & 3) * 16) ^ ((r1c & 6) << 3));

    auto issue = [&](int c) {
        const uint32_t st = sbase + (uint32_t)(c & 1) * 16384u;
        const int kb = c * 32;
        cp16(st + sw0,         g_x16 + (size_t)(b0 + r0c) * DM + kb + cbe);
        cp16(st + sw1,         g_x16 + (size_t)(b0 + r1c) * DM + kb + cbe);
        cp16(st + 8192 + sw0,  g_v16 + (size_t)(n0 + r0c) * DM + kb + cbe);
        cp16(st + 8192 + sw1,  g_v16 + (size_t)(n0 + r1c) * DM + kb + cbe);
        cp_commit();
    };

    const int a_row = wm + (lane & 15);
    const int a_kc  = (lane >> 4) * 16;
    const int b_row = wn + (lane & 7) + ((lane >> 4) << 3);
    const int b_kc  = ((lane >> 3) & 1) * 16;

    issue(0);

    for (int c = 0; c < 64; ++c) {
        if (c < 63) issue(c + 1);
        if (c < 63) cp_wait<1>(); else cp_wait<0>();
        __syncthreads();

        const uint32_t st = sbase + (uint32_t)(c & 1) * 16384u;

        #pragma unroll
        for (int k16 = 0; k16 < 2; ++k16) {
            const int koff = k16 * 32;
            uint32_t bh[4][4];
            #pragma unroll
            for (int q = 0; q < 4; ++q) {
                int row = b_row + q * 16;
                uint32_t sw = (uint32_t)row * 64 +
                              (uint32_t)((koff + b_kc) ^ ((row & 6) << 3));
                ldsm4(bh[q], st + 8192 + sw);
            }
            #pragma unroll
            for (int mb = 0; mb < 2; ++mb) {
                int row = a_row + mb * 16;
                uint32_t sw = (uint32_t)row * 64 +
                              (uint32_t)((koff + a_kc) ^ ((row & 6) << 3));
                uint32_t ah[4];
                ldsm4(ah, st + sw);
                #pragma unroll
                for (int q = 0; q < 4; ++q) {
                    mma_f16(d[mb][q*2],   ah, &bh[q][0]);
                    mma_f16(d[mb][q*2+1], ah, &bh[q][2]);
                }
            }
        }
        __syncthreads();
    }

    const int g = lane >> 2, t = lane & 3;
    #pragma unroll
    for (int mb = 0; mb < 2; ++mb) {
        #pragma unroll
        for (int half = 0; half < 2; ++half) {
            const int b = b0 + wm + mb * 16 + g + half * 8;
            #pragma unroll
            for (int ni = 0; ni < 8; ++ni) {
                const int colg = n0 + wn + ni * 8 + t * 2;
                const float gv = __ldg(&gate[b * NT + (colg >> 5)]);
                __half2 h2 = __floats2half2_rn(d[mb][ni][half*2+0] * gv,
                                               d[mb][ni][half*2+1] * gv);
                *(uint32_t*)(g_gv16 + (size_t)b * DM + colg) = *(const uint32_t*)&h2;
            }
        }
    }
}

// ---------------------------------------------------------------------------
// Launch 4: GEMM2 (out = GVx @ Wt) + frobenius folded into block (0,0).
// Identical to R16 except sv sums 8 (not 16) V-partials per transform.
// ---------------------------------------------------------------------------
__global__ __launch_bounds__(256) void gemm2_frob(
    float* __restrict__ outf, float* __restrict__ frob)
{
    extern __shared__ char sm[];
    const uint32_t sbase = smem_u32(sm);

    const int tid  = threadIdx.x;

    if (blockIdx.x == 0 && blockIdx.y == 0 && tid < NT) {
        int n = tid;
        float su = 0.0f, sv = 0.0f;
        #pragma unroll
        for (int j = 0; j < 16; j++) su += g_upart[n * 16 + j];
        #pragma unroll
        for (int j = 0; j < 8; j++) sv += g_vpart[n * 8 + j];
        frob[n] = sqrtf(su) * sqrtf(sv) * (1.0f / 256.0f);
    }

    const int wid  = tid >> 5;
    const int lane = tid & 31;
    const int n0 = blockIdx.x * 128;
    const int b0 = blockIdx.y * 128;
    const int wm = (wid & 3) * 32;
    const int wn = (wid >> 2) * 64;

    float d[2][8][4];
    #pragma unroll
    for (int i = 0; i < 2; i++)
        #pragma unroll
        for (int j = 0; j < 8; j++)
            #pragma unroll
            for (int r = 0; r < 4; r++) d[i][j][r] = 0.0f;

    const int r0c = tid >> 2;
    const int r1c = 64 + (tid >> 2);
    const int cbe = (tid & 3) * 8;
    const uint32_t sw0 = (uint32_t)r0c * 64 + (((tid & 3) * 16) ^ ((r0c & 6) << 3));
    const uint32_t sw1 = (uint32_t)r1c * 64 + (((tid & 3) * 16) ^ ((r1c & 6) << 3));

    auto issue = [&](int c) {
        const uint32_t st = sbase + (uint32_t)(c & 1) * 16384u;
        const int kb = c * 32;
        cp16(st + sw0,         g_gv16 + (size_t)(b0 + r0c) * DM + kb + cbe);
        cp16(st + sw1,         g_gv16 + (size_t)(b0 + r1c) * DM + kb + cbe);
        cp16(st + 8192 + sw0,  g_w16 + (size_t)(n0 + r0c) * DM + kb + cbe);
        cp16(st + 8192 + sw1,  g_w16 + (size_t)(n0 + r1c) * DM + kb + cbe);
        cp_commit();
    };

    const int a_row = wm + (lane & 15);
    const int a_kc  = (lane >> 4) * 16;
    const int b_row = wn + (lane & 7) + ((lane >> 4) << 3);
    const int b_kc  = ((lane >> 3) & 1) * 16;

    issue(0);

    for (int c = 0; c < 64; ++c) {
        if (c < 63) issue(c + 1);
        if (c < 63) cp_wait<1>(); else cp_wait<0>();
        __syncthreads();

        const uint32_t st = sbase + (uint32_t)(c & 1) * 16384u;

        #pragma unroll
        for (int k16 = 0; k16 < 2; ++k16) {
            const int koff = k16 * 32;
            uint32_t bh[4][4];
            #pragma unroll
            for (int q = 0; q < 4; ++q) {
                int row = b_row + q * 16;
                uint32_t sw = (uint32_t)row * 64 +
                              (uint32_t)((koff + b_kc) ^ ((row & 6) << 3));
                ldsm4(bh[q], st + 8192 + sw);
            }
            #pragma unroll
            for (int mb = 0; mb < 2; ++mb) {
                int row = a_row + mb * 16;
                uint32_t sw = (uint32_t)row * 64 +
                              (uint32_t)((koff + a_kc) ^ ((row & 6) << 3));
                uint32_t ah[4];
                ldsm4(ah, st + sw);
                #pragma unroll
                for (int q = 0; q < 4; ++q) {
                    mma_f16(d[mb][q*2],   ah, &bh[q][0]);
                    mma_f16(d[mb][q*2+1], ah, &bh[q][2]);
                }
            }
        }
        __syncthreads();
    }

    const int g = lane >> 2, t = lane & 3;
    #pragma unroll
    for (int mb = 0; mb < 2; ++mb) {
        #pragma unroll
        for (int half = 0; half < 2; ++half) {
            const int b = b0 + wm + mb * 16 + g + half * 8;
            #pragma unroll
            for (int ni = 0; ni < 8; ++ni) {
                const int colg = n0 + wn + ni * 8 + t * 2;
                *(float2*)(outf + (size_t)b * DM + colg) =
                    make_float2(d[mb][ni][half*2+0], d[mb][ni][half*2+1]);
            }
        }
    }
}

// ---------------------------------------------------------------------------
// d_out layout: [output 2048*2048 | gate 2048*64 | frob 64]
// ---------------------------------------------------------------------------
extern "C" void kernel_launch(void* const* d_in, const int* in_sizes, int n_in,
                              void* d_out, int out_size)
{
    const float* x    = (const float*)d_in[0];  // (2048, 2048)
    const float* Vw   = (const float*)d_in[1];  // (64, 32, 2048)
    const float* Uw   = (const float*)d_in[2];  // (64, 2048, 32)
    const float* enc  = (const float*)d_in[3];  // (64, 2048)
    const float* bias = (const float*)d_in[4];  // (64,)

    float* out  = (float*)d_out;
    float* gate = out + BATCH * DM;
    float* frob = gate + BATCH * NT;

    cudaFuncSetAttribute(gemm1_prepu, cudaFuncAttributeMaxDynamicSharedMemorySize, MMA_SMEM);
    cudaFuncSetAttribute(gemm2_frob, cudaFuncAttributeMaxDynamicSharedMemorySize, MMA_SMEM);

    gate_prep<<<1152, 256>>>(x, enc, (const float4*)x, (const float4*)Vw);
    gate_reduce<<<128, 256>>>(bias, gate);
    gemm1_prepu<<<1280, 256, MMA_SMEM>>>(gate, Uw);
    gemm2_frob<<<dim3(16, 16), 256, MMA_SMEM>>>(out, frob);
}